// round 8
// baseline (speedup 1.0000x reference)
#include <cuda_runtime.h>
#include <cstdint>

// 2-layer LSTM (H=50) + FC. B=4096, T=512, in-dim 1.
// R6 = R2 (best known: 400 thr, gate-packed f32x2, bcast weights, v4 h loads)
// with NON-VOLATILE inner-loop loads + explicit +1 prefetch so ptxas can
// software-pipeline LDS latency under the 8 FFMA2 chains.

typedef unsigned long long u64;

#define HID   50
#define BT    32
#define NT    400
#define TLEN  512

// byte offsets into dynamic smem
#define OFF_WP0 0          // packed w_hh0  [50j][50k] float4 = 40000
#define OFF_WPA 40000      // packed w_ih1
#define OFF_WPB 80000      // packed w_hh1
#define OFF_H1  120000     // h1 double buffer: 2 x (50k * 32b * 4B = 6400)
#define OFF_H2  132800     // h2 double buffer
#define OFF_XS  145600     // x chunk: 64 steps x 32 batches x 4 = 8192
#define OFF_B0  153792     // packed bias l1: float4[50]
#define OFF_B1  154592     // packed bias l2
#define OFF_WX  155392     // packed w_ih0: float4[50]
#define OFF_FCW 156192     // fc weights: 50 floats
#define SMEM_BYTES 156416

#define HBUF 6400          // bytes per h buffer

__device__ __forceinline__ u64 pk2(float lo, float hi) {
    u64 r; asm("mov.b64 %0, {%1, %2};" : "=l"(r) : "f"(lo), "f"(hi)); return r;
}
__device__ __forceinline__ void upk2(u64 v, float& lo, float& hi) {
    asm("mov.b64 {%0, %1}, %2;" : "=f"(lo), "=f"(hi) : "l"(v));
}
__device__ __forceinline__ void ffma2(u64& d, u64 a, u64 b) {
    asm("fma.rn.f32x2 %0, %1, %2, %0;" : "+l"(d) : "l"(a), "l"(b));
}
__device__ __forceinline__ float fsig(float v) {
    return __fdividef(1.0f, 1.0f + __expf(-v));
}
__device__ __forceinline__ float ftanh(float v) {
    return __fdividef(2.0f, 1.0f + __expf(-2.0f * v)) - 1.0f;
}

// 50-step gate-packed GEMV with +1 software prefetch (plain loads so ptxas
// may hoist/pipeline further).
__device__ __forceinline__ void gemm50(const char* __restrict__ wb,
                                       const char* __restrict__ hb,
                                       u64 aif[4], u64 ago[4]) {
    ulonglong2 w = *(const ulonglong2*)wb;
    float4     h = *(const float4*)hb;
#pragma unroll
    for (int k = 0; k < HID; ++k) {
        ulonglong2 wn;
        float4     hn;
        if (k + 1 < HID) {
            wn = *(const ulonglong2*)(wb + 16 * (k + 1));
            hn = *(const float4*)(hb + 128 * (k + 1));
        }
        u64 hh;
        hh = pk2(h.x, h.x); ffma2(aif[0], w.x, hh); ffma2(ago[0], w.y, hh);
        hh = pk2(h.y, h.y); ffma2(aif[1], w.x, hh); ffma2(ago[1], w.y, hh);
        hh = pk2(h.z, h.z); ffma2(aif[2], w.x, hh); ffma2(ago[2], w.y, hh);
        hh = pk2(h.w, h.w); ffma2(aif[3], w.x, hh); ffma2(ago[3], w.y, hh);
        w = wn; h = hn;
    }
}

__device__ __forceinline__ void act_update(const u64 aif[4], const u64 ago[4],
                                           float c[4], float hv[4]) {
#pragma unroll
    for (int r = 0; r < 4; ++r) {
        float pi, pf, pg, po;
        upk2(aif[r], pi, pf);
        upk2(ago[r], pg, po);
        float iv = fsig(pi);
        float fv = fsig(pf);
        float gv = ftanh(pg);
        float ov = fsig(po);
        c[r]  = fv * c[r] + iv * gv;
        hv[r] = ov * ftanh(c[r]);
    }
}

extern __shared__ float smem[];

__global__ __launch_bounds__(NT, 1) void lstm2_kernel(
    const float* __restrict__ x,
    const float* __restrict__ w_ih0, const float* __restrict__ w_hh0,
    const float* __restrict__ b_ih0, const float* __restrict__ b_hh0,
    const float* __restrict__ w_ih1, const float* __restrict__ w_hh1,
    const float* __restrict__ b_ih1, const float* __restrict__ b_hh1,
    const float* __restrict__ fc_w,  const float* __restrict__ fc_b,
    float* __restrict__ out)
{
    char* sb = (char*)smem;
    const int tid   = threadIdx.x;
    const int bbase = blockIdx.x * BT;

    // ---- stage packed weights: wp[j][k] = (Wi[j][k], Wf, Wg, Wo) ----
    {
        float4* wp0 = (float4*)(sb + OFF_WP0);
        float4* wpA = (float4*)(sb + OFF_WPA);
        float4* wpB = (float4*)(sb + OFF_WPB);
        for (int idx = tid; idx < HID * HID; idx += NT) {
            int jj = idx / HID, kk = idx - jj * HID;
            int r0 = jj * HID + kk;
            wp0[idx] = make_float4(w_hh0[r0], w_hh0[r0 + 50 * HID],
                                   w_hh0[r0 + 100 * HID], w_hh0[r0 + 150 * HID]);
            wpA[idx] = make_float4(w_ih1[r0], w_ih1[r0 + 50 * HID],
                                   w_ih1[r0 + 100 * HID], w_ih1[r0 + 150 * HID]);
            wpB[idx] = make_float4(w_hh1[r0], w_hh1[r0 + 50 * HID],
                                   w_hh1[r0 + 100 * HID], w_hh1[r0 + 150 * HID]);
        }
        float4* b0p = (float4*)(sb + OFF_B0);
        float4* b1p = (float4*)(sb + OFF_B1);
        float4* wxp = (float4*)(sb + OFF_WX);
        float*  fcs = (float*)(sb + OFF_FCW);
        for (int g = tid; g < HID; g += NT) {
            b0p[g] = make_float4(b_ih0[g]       + b_hh0[g],
                                 b_ih0[g + 50]  + b_hh0[g + 50],
                                 b_ih0[g + 100] + b_hh0[g + 100],
                                 b_ih0[g + 150] + b_hh0[g + 150]);
            b1p[g] = make_float4(b_ih1[g]       + b_hh1[g],
                                 b_ih1[g + 50]  + b_hh1[g + 50],
                                 b_ih1[g + 100] + b_hh1[g + 100],
                                 b_ih1[g + 150] + b_hh1[g + 150]);
            wxp[g] = make_float4(w_ih0[g], w_ih0[g + 50],
                                 w_ih0[g + 100], w_ih0[g + 150]);
            fcs[g] = fc_w[g];
        }
        float* hz = (float*)(sb + OFF_H1);
        for (int idx = tid; idx < 6400; idx += NT) hz[idx] = 0.0f;  // h1+h2 bufs
    }
    __syncthreads();

    // ---- per-thread mapping ----
    const int bg = tid & 7;     // batch group: batches 4*bg .. 4*bg+3
    const int j  = tid >> 3;    // hidden unit (0..49)

    u64 b0if, b0go, b1if, b1go, wxif, wxgo;
    {
        float4 t4 = ((float4*)(sb + OFF_B0))[j];
        b0if = pk2(t4.x, t4.y); b0go = pk2(t4.z, t4.w);
        t4 = ((float4*)(sb + OFF_B1))[j];
        b1if = pk2(t4.x, t4.y); b1go = pk2(t4.z, t4.w);
        t4 = ((float4*)(sb + OFF_WX))[j];
        wxif = pk2(t4.x, t4.y); wxgo = pk2(t4.z, t4.w);
    }

    const char* w0p = sb + OFF_WP0 + j * 800;
    const char* wAp = sb + OFF_WPA + j * 800;
    const char* wBp = sb + OFF_WPB + j * 800;
    const char* h1rd = sb + OFF_H1 + bg * 16;
    const char* h2rd = sb + OFF_H2 + bg * 16;
    const char* xrd  = sb + OFF_XS + bg * 16;

    float c1[4] = {0.f, 0.f, 0.f, 0.f};
    float c2[4] = {0.f, 0.f, 0.f, 0.f};
    float h1v[4], h2v[4];

    for (int t = 0; t < TLEN; ++t) {
        // stage 64-step x chunk (coalesced)
        if ((t & 63) == 0) {
            float* xs = (float*)(sb + OFF_XS);
            for (int idx = tid; idx < BT * 64; idx += NT) {
                int b = idx >> 6, tt = idx & 63;
                xs[tt * BT + b] = x[(bbase + b) * TLEN + t + tt];
            }
            __syncthreads();
        }

        const int cur = (t & 1) * HBUF;
        const int nxt = HBUF - cur;

        // ============ layer 1 ============
        u64 aif[4], ago[4];
        {
            float4 xv = *(const float4*)(xrd + (t & 63) * 128);
            u64 hh;
            hh = pk2(xv.x, xv.x); aif[0] = b0if; ffma2(aif[0], wxif, hh);
                                  ago[0] = b0go; ffma2(ago[0], wxgo, hh);
            hh = pk2(xv.y, xv.y); aif[1] = b0if; ffma2(aif[1], wxif, hh);
                                  ago[1] = b0go; ffma2(ago[1], wxgo, hh);
            hh = pk2(xv.z, xv.z); aif[2] = b0if; ffma2(aif[2], wxif, hh);
                                  ago[2] = b0go; ffma2(ago[2], wxgo, hh);
            hh = pk2(xv.w, xv.w); aif[3] = b0if; ffma2(aif[3], wxif, hh);
                                  ago[3] = b0go; ffma2(ago[3], wxgo, hh);
        }
        gemm50(w0p, h1rd + cur, aif, ago);
        act_update(aif, ago, c1, h1v);
        *(float4*)(sb + OFF_H1 + nxt + j * 128 + bg * 16) =
            make_float4(h1v[0], h1v[1], h1v[2], h1v[3]);
        __syncthreads();

        // ============ layer 2 ============
        aif[0] = b1if; aif[1] = b1if; aif[2] = b1if; aif[3] = b1if;
        ago[0] = b1go; ago[1] = b1go; ago[2] = b1go; ago[3] = b1go;
        gemm50(wAp, h1rd + nxt, aif, ago);   // input path: new h1
        gemm50(wBp, h2rd + cur, aif, ago);   // recurrent path: old h2
        act_update(aif, ago, c2, h2v);
        *(float4*)(sb + OFF_H2 + nxt + j * 128 + bg * 16) =
            make_float4(h2v[0], h2v[1], h2v[2], h2v[3]);
        __syncthreads();
    }

    // ---- final FC (last h2 lives in buffer 0 after t=511) ----
    if (tid < BT) {
        const float* h2f = (const float*)(sb + OFF_H2);
        const float* fcs = (const float*)(sb + OFF_FCW);
        float s = fc_b[0];
#pragma unroll 10
        for (int k = 0; k < HID; ++k) s += h2f[k * BT + tid] * fcs[k];
        out[bbase + tid] = s;
    }
}

extern "C" void kernel_launch(void* const* d_in, const int* in_sizes, int n_in,
                              void* d_out, int out_size) {
    const float* x     = (const float*)d_in[0];
    const float* w_ih0 = (const float*)d_in[1];
    const float* w_hh0 = (const float*)d_in[2];
    const float* b_ih0 = (const float*)d_in[3];
    const float* b_hh0 = (const float*)d_in[4];
    const float* w_ih1 = (const float*)d_in[5];
    const float* w_hh1 = (const float*)d_in[6];
    const float* b_ih1 = (const float*)d_in[7];
    const float* b_hh1 = (const float*)d_in[8];
    const float* fc_w  = (const float*)d_in[9];
    const float* fc_b  = (const float*)d_in[10];
    float* out = (float*)d_out;

    cudaFuncSetAttribute(lstm2_kernel,
                         cudaFuncAttributeMaxDynamicSharedMemorySize,
                         SMEM_BYTES);

    lstm2_kernel<<<4096 / BT, NT, SMEM_BYTES>>>(
        x, w_ih0, w_hh0, b_ih0, b_hh0,
        w_ih1, w_hh1, b_ih1, b_hh1, fc_w, fc_b, out);
}

// round 9
// speedup vs baseline: 1.0012x; 1.0012x over previous
#include <cuda_runtime.h>
#include <cstdint>

// 2-layer LSTM (H=50) + FC. B=4096, T=512, in-dim 1.
// R6 = R2 (best known: 400 thr, gate-packed f32x2, bcast weights, v4 h loads)
// with NON-VOLATILE inner-loop loads + explicit +1 prefetch so ptxas can
// software-pipeline LDS latency under the 8 FFMA2 chains.

typedef unsigned long long u64;

#define HID   50
#define BT    32
#define NT    400
#define TLEN  512

// byte offsets into dynamic smem
#define OFF_WP0 0          // packed w_hh0  [50j][50k] float4 = 40000
#define OFF_WPA 40000      // packed w_ih1
#define OFF_WPB 80000      // packed w_hh1
#define OFF_H1  120000     // h1 double buffer: 2 x (50k * 32b * 4B = 6400)
#define OFF_H2  132800     // h2 double buffer
#define OFF_XS  145600     // x chunk: 64 steps x 32 batches x 4 = 8192
#define OFF_B0  153792     // packed bias l1: float4[50]
#define OFF_B1  154592     // packed bias l2
#define OFF_WX  155392     // packed w_ih0: float4[50]
#define OFF_FCW 156192     // fc weights: 50 floats
#define SMEM_BYTES 156416

#define HBUF 6400          // bytes per h buffer

__device__ __forceinline__ u64 pk2(float lo, float hi) {
    u64 r; asm("mov.b64 %0, {%1, %2};" : "=l"(r) : "f"(lo), "f"(hi)); return r;
}
__device__ __forceinline__ void upk2(u64 v, float& lo, float& hi) {
    asm("mov.b64 {%0, %1}, %2;" : "=f"(lo), "=f"(hi) : "l"(v));
}
__device__ __forceinline__ void ffma2(u64& d, u64 a, u64 b) {
    asm("fma.rn.f32x2 %0, %1, %2, %0;" : "+l"(d) : "l"(a), "l"(b));
}
__device__ __forceinline__ float fsig(float v) {
    return __fdividef(1.0f, 1.0f + __expf(-v));
}
__device__ __forceinline__ float ftanh(float v) {
    return __fdividef(2.0f, 1.0f + __expf(-2.0f * v)) - 1.0f;
}

// 50-step gate-packed GEMV with +1 software prefetch (plain loads so ptxas
// may hoist/pipeline further).
__device__ __forceinline__ void gemm50(const char* __restrict__ wb,
                                       const char* __restrict__ hb,
                                       u64 aif[4], u64 ago[4]) {
    ulonglong2 w = *(const ulonglong2*)wb;
    float4     h = *(const float4*)hb;
#pragma unroll
    for (int k = 0; k < HID; ++k) {
        ulonglong2 wn;
        float4     hn;
        if (k + 1 < HID) {
            wn = *(const ulonglong2*)(wb + 16 * (k + 1));
            hn = *(const float4*)(hb + 128 * (k + 1));
        }
        u64 hh;
        hh = pk2(h.x, h.x); ffma2(aif[0], w.x, hh); ffma2(ago[0], w.y, hh);
        hh = pk2(h.y, h.y); ffma2(aif[1], w.x, hh); ffma2(ago[1], w.y, hh);
        hh = pk2(h.z, h.z); ffma2(aif[2], w.x, hh); ffma2(ago[2], w.y, hh);
        hh = pk2(h.w, h.w); ffma2(aif[3], w.x, hh); ffma2(ago[3], w.y, hh);
        w = wn; h = hn;
    }
}

__device__ __forceinline__ void act_update(const u64 aif[4], const u64 ago[4],
                                           float c[4], float hv[4]) {
#pragma unroll
    for (int r = 0; r < 4; ++r) {
        float pi, pf, pg, po;
        upk2(aif[r], pi, pf);
        upk2(ago[r], pg, po);
        float iv = fsig(pi);
        float fv = fsig(pf);
        float gv = ftanh(pg);
        float ov = fsig(po);
        c[r]  = fv * c[r] + iv * gv;
        hv[r] = ov * ftanh(c[r]);
    }
}

extern __shared__ float smem[];

__global__ __launch_bounds__(NT, 1) void lstm2_kernel(
    const float* __restrict__ x,
    const float* __restrict__ w_ih0, const float* __restrict__ w_hh0,
    const float* __restrict__ b_ih0, const float* __restrict__ b_hh0,
    const float* __restrict__ w_ih1, const float* __restrict__ w_hh1,
    const float* __restrict__ b_ih1, const float* __restrict__ b_hh1,
    const float* __restrict__ fc_w,  const float* __restrict__ fc_b,
    float* __restrict__ out)
{
    char* sb = (char*)smem;
    const int tid   = threadIdx.x;
    const int bbase = blockIdx.x * BT;

    // ---- stage packed weights: wp[j][k] = (Wi[j][k], Wf, Wg, Wo) ----
    {
        float4* wp0 = (float4*)(sb + OFF_WP0);
        float4* wpA = (float4*)(sb + OFF_WPA);
        float4* wpB = (float4*)(sb + OFF_WPB);
        for (int idx = tid; idx < HID * HID; idx += NT) {
            int jj = idx / HID, kk = idx - jj * HID;
            int r0 = jj * HID + kk;
            wp0[idx] = make_float4(w_hh0[r0], w_hh0[r0 + 50 * HID],
                                   w_hh0[r0 + 100 * HID], w_hh0[r0 + 150 * HID]);
            wpA[idx] = make_float4(w_ih1[r0], w_ih1[r0 + 50 * HID],
                                   w_ih1[r0 + 100 * HID], w_ih1[r0 + 150 * HID]);
            wpB[idx] = make_float4(w_hh1[r0], w_hh1[r0 + 50 * HID],
                                   w_hh1[r0 + 100 * HID], w_hh1[r0 + 150 * HID]);
        }
        float4* b0p = (float4*)(sb + OFF_B0);
        float4* b1p = (float4*)(sb + OFF_B1);
        float4* wxp = (float4*)(sb + OFF_WX);
        float*  fcs = (float*)(sb + OFF_FCW);
        for (int g = tid; g < HID; g += NT) {
            b0p[g] = make_float4(b_ih0[g]       + b_hh0[g],
                                 b_ih0[g + 50]  + b_hh0[g + 50],
                                 b_ih0[g + 100] + b_hh0[g + 100],
                                 b_ih0[g + 150] + b_hh0[g + 150]);
            b1p[g] = make_float4(b_ih1[g]       + b_hh1[g],
                                 b_ih1[g + 50]  + b_hh1[g + 50],
                                 b_ih1[g + 100] + b_hh1[g + 100],
                                 b_ih1[g + 150] + b_hh1[g + 150]);
            wxp[g] = make_float4(w_ih0[g], w_ih0[g + 50],
                                 w_ih0[g + 100], w_ih0[g + 150]);
            fcs[g] = fc_w[g];
        }
        float* hz = (float*)(sb + OFF_H1);
        for (int idx = tid; idx < 6400; idx += NT) hz[idx] = 0.0f;  // h1+h2 bufs
    }
    __syncthreads();

    // ---- per-thread mapping ----
    const int bg = tid & 7;     // batch group: batches 4*bg .. 4*bg+3
    const int j  = tid >> 3;    // hidden unit (0..49)

    u64 b0if, b0go, b1if, b1go, wxif, wxgo;
    {
        float4 t4 = ((float4*)(sb + OFF_B0))[j];
        b0if = pk2(t4.x, t4.y); b0go = pk2(t4.z, t4.w);
        t4 = ((float4*)(sb + OFF_B1))[j];
        b1if = pk2(t4.x, t4.y); b1go = pk2(t4.z, t4.w);
        t4 = ((float4*)(sb + OFF_WX))[j];
        wxif = pk2(t4.x, t4.y); wxgo = pk2(t4.z, t4.w);
    }

    const char* w0p = sb + OFF_WP0 + j * 800;
    const char* wAp = sb + OFF_WPA + j * 800;
    const char* wBp = sb + OFF_WPB + j * 800;
    const char* h1rd = sb + OFF_H1 + bg * 16;
    const char* h2rd = sb + OFF_H2 + bg * 16;
    const char* xrd  = sb + OFF_XS + bg * 16;

    float c1[4] = {0.f, 0.f, 0.f, 0.f};
    float c2[4] = {0.f, 0.f, 0.f, 0.f};
    float h1v[4], h2v[4];

    for (int t = 0; t < TLEN; ++t) {
        // stage 64-step x chunk (coalesced)
        if ((t & 63) == 0) {
            float* xs = (float*)(sb + OFF_XS);
            for (int idx = tid; idx < BT * 64; idx += NT) {
                int b = idx >> 6, tt = idx & 63;
                xs[tt * BT + b] = x[(bbase + b) * TLEN + t + tt];
            }
            __syncthreads();
        }

        const int cur = (t & 1) * HBUF;
        const int nxt = HBUF - cur;

        // ============ layer 1 ============
        u64 aif[4], ago[4];
        {
            float4 xv = *(const float4*)(xrd + (t & 63) * 128);
            u64 hh;
            hh = pk2(xv.x, xv.x); aif[0] = b0if; ffma2(aif[0], wxif, hh);
                                  ago[0] = b0go; ffma2(ago[0], wxgo, hh);
            hh = pk2(xv.y, xv.y); aif[1] = b0if; ffma2(aif[1], wxif, hh);
                                  ago[1] = b0go; ffma2(ago[1], wxgo, hh);
            hh = pk2(xv.z, xv.z); aif[2] = b0if; ffma2(aif[2], wxif, hh);
                                  ago[2] = b0go; ffma2(ago[2], wxgo, hh);
            hh = pk2(xv.w, xv.w); aif[3] = b0if; ffma2(aif[3], wxif, hh);
                                  ago[3] = b0go; ffma2(ago[3], wxgo, hh);
        }
        gemm50(w0p, h1rd + cur, aif, ago);
        act_update(aif, ago, c1, h1v);
        *(float4*)(sb + OFF_H1 + nxt + j * 128 + bg * 16) =
            make_float4(h1v[0], h1v[1], h1v[2], h1v[3]);
        __syncthreads();

        // ============ layer 2 ============
        aif[0] = b1if; aif[1] = b1if; aif[2] = b1if; aif[3] = b1if;
        ago[0] = b1go; ago[1] = b1go; ago[2] = b1go; ago[3] = b1go;
        gemm50(wAp, h1rd + nxt, aif, ago);   // input path: new h1
        gemm50(wBp, h2rd + cur, aif, ago);   // recurrent path: old h2
        act_update(aif, ago, c2, h2v);
        *(float4*)(sb + OFF_H2 + nxt + j * 128 + bg * 16) =
            make_float4(h2v[0], h2v[1], h2v[2], h2v[3]);
        __syncthreads();
    }

    // ---- final FC (last h2 lives in buffer 0 after t=511) ----
    if (tid < BT) {
        const float* h2f = (const float*)(sb + OFF_H2);
        const float* fcs = (const float*)(sb + OFF_FCW);
        float s = fc_b[0];
#pragma unroll 10
        for (int k = 0; k < HID; ++k) s += h2f[k * BT + tid] * fcs[k];
        out[bbase + tid] = s;
    }
}

extern "C" void kernel_launch(void* const* d_in, const int* in_sizes, int n_in,
                              void* d_out, int out_size) {
    const float* x     = (const float*)d_in[0];
    const float* w_ih0 = (const float*)d_in[1];
    const float* w_hh0 = (const float*)d_in[2];
    const float* b_ih0 = (const float*)d_in[3];
    const float* b_hh0 = (const float*)d_in[4];
    const float* w_ih1 = (const float*)d_in[5];
    const float* w_hh1 = (const float*)d_in[6];
    const float* b_ih1 = (const float*)d_in[7];
    const float* b_hh1 = (const float*)d_in[8];
    const float* fc_w  = (const float*)d_in[9];
    const float* fc_b  = (const float*)d_in[10];
    float* out = (float*)d_out;

    cudaFuncSetAttribute(lstm2_kernel,
                         cudaFuncAttributeMaxDynamicSharedMemorySize,
                         SMEM_BYTES);

    lstm2_kernel<<<4096 / BT, NT, SMEM_BYTES>>>(
        x, w_ih0, w_hh0, b_ih0, b_hh0,
        w_ih1, w_hh1, b_ih1, b_hh1, fc_w, fc_b, out);
}

// round 10
// speedup vs baseline: 1.0738x; 1.0725x over previous
#include <cuda_runtime.h>
#include <cstdint>

// 2-layer LSTM (H=50) + FC. B=4096, T=512, in-dim 1.
// R10: two INDEPENDENT 16-batch groups per CTA (7 warps each, named barriers
// 1/2), phase-shifted so one group's FFMA2 gemm fills the other's MUFU/act/
// barrier bubbles. Shared weight tiles (stride 912B: conflict-free for the
// 8-distinct-j-per-warp mapping). Inner loop unchanged from R2/R6.

typedef unsigned long long u64;

#define HID   50
#define BT    32
#define NT    448      // 14 warps = 2 groups x 7 warps (224 thr, 200 active)
#define GSZ   224
#define TLEN  512
#define WST   912      // weight row stride bytes (912 % 128 == 16)

// byte offsets into dynamic smem
#define OFF_W0  0                   // w_hh0  [50j][50k] float4 @ stride 912 = 45600
#define OFF_WA  45600               // w_ih1
#define OFF_WB  91200               // w_hh1
#define OFF_H1G 136800              // h1: per group 2x3200 double buf (g*12800)
#define OFF_H2G 143200              // h2: per group (g*12800)
#define OFF_XG  162400              // x chunk per group: 64*16*4 = 4096 (g*4096)
#define OFF_B0  170592              // packed bias l1: float4[50]
#define OFF_B1  171392
#define OFF_WX  172192
#define OFF_FCW 172992              // 50 floats
#define SMEM_BYTES 173248

#define HBUF 3200                   // bytes per h buffer (50k x 16b x 4B)
#define GSTRIDE 12800               // per-group h region stride (2 bufs x 2... = 4*3200)

__device__ __forceinline__ u64 pk2(float lo, float hi) {
    u64 r; asm("mov.b64 %0, {%1, %2};" : "=l"(r) : "f"(lo), "f"(hi)); return r;
}
__device__ __forceinline__ void upk2(u64 v, float& lo, float& hi) {
    asm("mov.b64 {%0, %1}, %2;" : "=f"(lo), "=f"(hi) : "l"(v));
}
__device__ __forceinline__ void ffma2(u64& d, u64 a, u64 b) {
    asm("fma.rn.f32x2 %0, %1, %2, %0;" : "+l"(d) : "l"(a), "l"(b));
}
__device__ __forceinline__ float fsig(float v) {
    return __fdividef(1.0f, 1.0f + __expf(-v));
}
__device__ __forceinline__ float ftanh(float v) {
    return __fdividef(2.0f, 1.0f + __expf(-2.0f * v)) - 1.0f;
}
__device__ __forceinline__ void gbar(int id) {
    asm volatile("bar.sync %0, %1;" :: "r"(id), "r"(GSZ) : "memory");
}

// 50-step gate-packed GEMV: acc += W[j][k] * h[k] (4 batches, 2 gate-pairs)
__device__ __forceinline__ void gemm50(const char* __restrict__ wb,
                                       const char* __restrict__ hb,
                                       u64 aif[4], u64 ago[4]) {
#pragma unroll
    for (int k = 0; k < HID; ++k) {
        ulonglong2 w = *(const ulonglong2*)(wb + 16 * k);
        float4 h = *(const float4*)(hb + 64 * k);
        u64 hh;
        hh = pk2(h.x, h.x); ffma2(aif[0], w.x, hh); ffma2(ago[0], w.y, hh);
        hh = pk2(h.y, h.y); ffma2(aif[1], w.x, hh); ffma2(ago[1], w.y, hh);
        hh = pk2(h.z, h.z); ffma2(aif[2], w.x, hh); ffma2(ago[2], w.y, hh);
        hh = pk2(h.w, h.w); ffma2(aif[3], w.x, hh); ffma2(ago[3], w.y, hh);
    }
}

__device__ __forceinline__ void act_update(const u64 aif[4], const u64 ago[4],
                                           float c[4], float hv[4]) {
#pragma unroll
    for (int r = 0; r < 4; ++r) {
        float pi, pf, pg, po;
        upk2(aif[r], pi, pf);
        upk2(ago[r], pg, po);
        float iv = fsig(pi);
        float fv = fsig(pf);
        float gv = ftanh(pg);
        float ov = fsig(po);
        c[r]  = fv * c[r] + iv * gv;
        hv[r] = ov * ftanh(c[r]);
    }
}

extern __shared__ float smem[];

__global__ __launch_bounds__(NT, 1) void lstm2_kernel(
    const float* __restrict__ x,
    const float* __restrict__ w_ih0, const float* __restrict__ w_hh0,
    const float* __restrict__ b_ih0, const float* __restrict__ b_hh0,
    const float* __restrict__ w_ih1, const float* __restrict__ w_hh1,
    const float* __restrict__ b_ih1, const float* __restrict__ b_hh1,
    const float* __restrict__ fc_w,  const float* __restrict__ fc_b,
    float* __restrict__ out)
{
    char* sb = (char*)smem;
    const int tid   = threadIdx.x;
    const int bbase = blockIdx.x * BT;

    // ---- stage packed weights: row j (stride 912B), entry k = float4(i,f,g,o) ----
    for (int idx = tid; idx < HID * HID; idx += NT) {
        int jj = idx / HID, kk = idx - jj * HID;
        int r0 = jj * HID + kk;
        *(float4*)(sb + OFF_W0 + jj * WST + kk * 16) =
            make_float4(w_hh0[r0], w_hh0[r0 + 2500], w_hh0[r0 + 5000], w_hh0[r0 + 7500]);
        *(float4*)(sb + OFF_WA + jj * WST + kk * 16) =
            make_float4(w_ih1[r0], w_ih1[r0 + 2500], w_ih1[r0 + 5000], w_ih1[r0 + 7500]);
        *(float4*)(sb + OFF_WB + jj * WST + kk * 16) =
            make_float4(w_hh1[r0], w_hh1[r0 + 2500], w_hh1[r0 + 5000], w_hh1[r0 + 7500]);
    }
    for (int g = tid; g < HID; g += NT) {
        ((float4*)(sb + OFF_B0))[g] =
            make_float4(b_ih0[g] + b_hh0[g],       b_ih0[g + 50]  + b_hh0[g + 50],
                        b_ih0[g + 100] + b_hh0[g + 100], b_ih0[g + 150] + b_hh0[g + 150]);
        ((float4*)(sb + OFF_B1))[g] =
            make_float4(b_ih1[g] + b_hh1[g],       b_ih1[g + 50]  + b_hh1[g + 50],
                        b_ih1[g + 100] + b_hh1[g + 100], b_ih1[g + 150] + b_hh1[g + 150]);
        ((float4*)(sb + OFF_WX))[g] =
            make_float4(w_ih0[g], w_ih0[g + 50], w_ih0[g + 100], w_ih0[g + 150]);
        ((float*)(sb + OFF_FCW))[g] = fc_w[g];
    }
    // zero all h buffers (2 groups x (h1+h2) x double = 25600 B)
    for (int idx = tid; idx < 6400; idx += NT)
        ((float*)(sb + OFF_H1G))[idx] = 0.0f;
    __syncthreads();

    // ---- group & thread mapping ----
    const int grp   = (tid >= GSZ);          // 0 or 1
    const int gtid  = tid - grp * GSZ;       // 0..223
    const bool active = (gtid < 200);
    const int bg    = gtid & 3;              // batch group (4 batches of 16)
    const int j     = active ? (gtid >> 2) : 0;  // hidden unit 0..49
    const int barid = 1 + grp;

    u64 b0if, b0go, b1if, b1go, wxif, wxgo;
    {
        float4 t4 = ((float4*)(sb + OFF_B0))[j];
        b0if = pk2(t4.x, t4.y); b0go = pk2(t4.z, t4.w);
        t4 = ((float4*)(sb + OFF_B1))[j];
        b1if = pk2(t4.x, t4.y); b1go = pk2(t4.z, t4.w);
        t4 = ((float4*)(sb + OFF_WX))[j];
        wxif = pk2(t4.x, t4.y); wxgo = pk2(t4.z, t4.w);
    }

    const char* w0p = sb + OFF_W0 + j * WST;
    const char* wAp = sb + OFF_WA + j * WST;
    const char* wBp = sb + OFF_WB + j * WST;
    char* h1b = sb + OFF_H1G + grp * GSTRIDE;      // this group's h1 double buffer
    char* h2b = sb + OFF_H2G + grp * GSTRIDE;      // this group's h2 double buffer
    float* xs = (float*)(sb + OFF_XG + grp * 4096);
    const int hrd = bg * 16;                        // batch offset within tile

    float c1[4] = {0.f, 0.f, 0.f, 0.f};
    float c2[4] = {0.f, 0.f, 0.f, 0.f};
    float h1v[4], h2v[4];

    for (int t = 0; t < TLEN; ++t) {
        // stage 64-step x chunk for this group's 16 batches
        if ((t & 63) == 0) {
            for (int idx = gtid; idx < 16 * 64; idx += GSZ) {
                int b = idx >> 6, tt = idx & 63;
                xs[tt * 16 + b] = x[(bbase + grp * 16 + b) * TLEN + t + tt];
            }
            gbar(barid);
        }

        const int cur = (t & 1) * HBUF;
        const int nxt = HBUF - cur;

        // ============ layer 1 ============
        u64 aif[4], ago[4];
        {
            float4 xv = *(const float4*)((char*)xs + (t & 63) * 64 + hrd);
            u64 hh;
            hh = pk2(xv.x, xv.x); aif[0] = b0if; ffma2(aif[0], wxif, hh);
                                  ago[0] = b0go; ffma2(ago[0], wxgo, hh);
            hh = pk2(xv.y, xv.y); aif[1] = b0if; ffma2(aif[1], wxif, hh);
                                  ago[1] = b0go; ffma2(ago[1], wxgo, hh);
            hh = pk2(xv.z, xv.z); aif[2] = b0if; ffma2(aif[2], wxif, hh);
                                  ago[2] = b0go; ffma2(ago[2], wxgo, hh);
            hh = pk2(xv.w, xv.w); aif[3] = b0if; ffma2(aif[3], wxif, hh);
                                  ago[3] = b0go; ffma2(ago[3], wxgo, hh);
        }
        gemm50(w0p, h1b + cur + hrd, aif, ago);
        act_update(aif, ago, c1, h1v);
        if (active)
            *(float4*)(h1b + nxt + j * 64 + bg * 16) =
                make_float4(h1v[0], h1v[1], h1v[2], h1v[3]);
        gbar(barid);

        // ============ layer 2 ============
        aif[0] = b1if; aif[1] = b1if; aif[2] = b1if; aif[3] = b1if;
        ago[0] = b1go; ago[1] = b1go; ago[2] = b1go; ago[3] = b1go;
        gemm50(wAp, h1b + nxt + hrd, aif, ago);   // input path: new h1
        gemm50(wBp, h2b + cur + hrd, aif, ago);   // recurrent path: old h2
        act_update(aif, ago, c2, h2v);
        if (active)
            *(float4*)(h2b + nxt + j * 64 + bg * 16) =
                make_float4(h2v[0], h2v[1], h2v[2], h2v[3]);
        gbar(barid);
    }

    // ---- final FC (last h2 in buffer 0 after t=511) ----
    __syncthreads();
    if (tid < BT) {
        const int b  = tid;
        const char* h2f = sb + OFF_H2G + (b >> 4) * GSTRIDE;   // that batch's group
        const int lb = b & 15;
        const float* fcs = (const float*)(sb + OFF_FCW);
        float s = fc_b[0];
#pragma unroll 10
        for (int k = 0; k < HID; ++k)
            s += *(const float*)(h2f + k * 64 + lb * 4) * fcs[k];
        out[bbase + b] = s;
    }
}

extern "C" void kernel_launch(void* const* d_in, const int* in_sizes, int n_in,
                              void* d_out, int out_size) {
    const float* x     = (const float*)d_in[0];
    const float* w_ih0 = (const float*)d_in[1];
    const float* w_hh0 = (const float*)d_in[2];
    const float* b_ih0 = (const float*)d_in[3];
    const float* b_hh0 = (const float*)d_in[4];
    const float* w_ih1 = (const float*)d_in[5];
    const float* w_hh1 = (const float*)d_in[6];
    const float* b_ih1 = (const float*)d_in[7];
    const float* b_hh1 = (const float*)d_in[8];
    const float* fc_w  = (const float*)d_in[9];
    const float* fc_b  = (const float*)d_in[10];
    float* out = (float*)d_out;

    cudaFuncSetAttribute(lstm2_kernel,
                         cudaFuncAttributeMaxDynamicSharedMemorySize,
                         SMEM_BYTES);

    lstm2_kernel<<<4096 / BT, NT, SMEM_BYTES>>>(
        x, w_ih0, w_hh0, b_ih0, b_hh0,
        w_ih1, w_hh1, b_ih1, b_hh1, fc_w, fc_b, out);
}

// round 13
// speedup vs baseline: 1.2338x; 1.1490x over previous
#include <cuda_runtime.h>
#include <cuda_fp16.h>
#include <cstdint>

// 2-layer LSTM (H=50) + FC. B=4096, T=512, in-dim 1.
// R13: mma.sync.m16n8k16 fp16 3-pass (hi/lo, lo x1024). Gate order n=4j+type;
// shfl.bfly(1) exchange; warp-local c. 13 warps x 2 n-tiles x 2 m-tiles.

typedef uint32_t u32;

#define NT    416
#define BT    32
#define TLEN  512

#define W1H_O 0         // 208 x 144B
#define W1L_O 29952
#define W2H_O 59904     // 208 x 240B
#define W2L_O 109824
#define A1_O  159744    // 4 x (32 x 144B)
#define A2_O  178176    // 4 x (32 x 240B)
#define FCW_O 208896
#define SMEM_BYTES 209408

#define A1RS 144
#define A2RS 240
#define W1RS 144
#define W2RS 240
#define A1T(buf, part) (A1_O + ((buf) * 2 + (part)) * 4608)
#define A2T(buf, part) (A2_O + ((buf) * 2 + (part)) * 7680)

__device__ __forceinline__ float fsig(float v) {
    return __fdividef(1.0f, 1.0f + __expf(-v));
}
__device__ __forceinline__ float ftanh(float v) {
    return __fdividef(2.0f, 1.0f + __expf(-2.0f * v)) - 1.0f;
}

__device__ __forceinline__ void mma16816(float d[4], const u32 a[4], u32 b0, u32 b1) {
    asm("mma.sync.aligned.m16n8k16.row.col.f32.f16.f16.f32 "
        "{%0,%1,%2,%3},{%4,%5,%6,%7},{%8,%9},{%0,%1,%2,%3};"
        : "+f"(d[0]), "+f"(d[1]), "+f"(d[2]), "+f"(d[3])
        : "r"(a[0]), "r"(a[1]), "r"(a[2]), "r"(a[3]), "r"(b0), "r"(b1));
}

__device__ __forceinline__ void sthalf2(char* bh, char* bl, int rs, int row, int col, float v) {
    __half hi = __float2half_rn(v);
    __half lo = __float2half_rn((v - __half2float(hi)) * 1024.0f);
    *(__half*)(bh + row * rs + col * 2) = hi;
    *(__half*)(bl + row * rs + col * 2) = lo;
}

template <int KS, int ARS, int WRS>
__device__ __forceinline__ void gemm_mma(
    const char* ah_b, const char* al_b, const char* wh_b, const char* wl_b,
    int n0A, int n0B, int g, int tq, float dm[2][2][4], float dc[2][2][4])
{
#pragma unroll
    for (int ks = 0; ks < KS; ++ks) {
        const int kb = ks * 32 + tq * 4;
        u32 ah[2][4], al[2][4];
#pragma unroll
        for (int mi = 0; mi < 2; ++mi) {
            const char* p = ah_b + (mi * 16 + g) * ARS + kb;
            ah[mi][0] = *(const u32*)(p);
            ah[mi][1] = *(const u32*)(p + 8 * ARS);
            ah[mi][2] = *(const u32*)(p + 16);
            ah[mi][3] = *(const u32*)(p + 8 * ARS + 16);
            const char* q = al_b + (mi * 16 + g) * ARS + kb;
            al[mi][0] = *(const u32*)(q);
            al[mi][1] = *(const u32*)(q + 8 * ARS);
            al[mi][2] = *(const u32*)(q + 16);
            al[mi][3] = *(const u32*)(q + 8 * ARS + 16);
        }
#pragma unroll
        for (int nn = 0; nn < 2; ++nn) {
            const int n0 = nn ? n0B : n0A;
            const char* pw = wh_b + (n0 + g) * WRS + kb;
            u32 bh0 = *(const u32*)pw, bh1 = *(const u32*)(pw + 16);
            const char* ql = wl_b + (n0 + g) * WRS + kb;
            u32 bl0 = *(const u32*)ql, bl1 = *(const u32*)(ql + 16);
#pragma unroll
            for (int mi = 0; mi < 2; ++mi) {
                mma16816(dm[nn][mi], ah[mi], bh0, bh1);
                mma16816(dc[nn][mi], al[mi], bh0, bh1);
                mma16816(dc[nn][mi], ah[mi], bl0, bl1);
            }
        }
    }
}

__device__ __forceinline__ void epi_act(
    float dm[2][2][4], float dc[2][2][4], int P, float sg, float mg, float bg,
    float c[2][2], float h[2][2])
{
    const float inv = 1.0f / 1024.0f;
    float v[2][2][4];
#pragma unroll
    for (int nt = 0; nt < 2; ++nt)
#pragma unroll
        for (int mi = 0; mi < 2; ++mi) {
            v[nt][mi][0] = mg * fsig(sg * (dm[nt][mi][0] + dc[nt][mi][0] * inv)) - bg;
            v[nt][mi][1] = fsig(dm[nt][mi][1] + dc[nt][mi][1] * inv);
            v[nt][mi][2] = mg * fsig(sg * (dm[nt][mi][2] + dc[nt][mi][2] * inv)) - bg;
            v[nt][mi][3] = fsig(dm[nt][mi][3] + dc[nt][mi][3] * inv);
        }
#pragma unroll
    for (int nt = 0; nt < 2; ++nt) {
        float own[4], rcv[4];
#pragma unroll
        for (int r = 0; r < 4; ++r) {
            float snd = P ? v[nt][0][r] : v[nt][1][r];
            rcv[r] = __shfl_xor_sync(0xffffffffu, snd, 1);
            own[r] = P ? v[nt][1][r] : v[nt][0][r];
        }
        float i0 = P ? rcv[0] : own[0], f0 = P ? rcv[1] : own[1];
        float g0 = P ? own[0] : rcv[0], o0 = P ? own[1] : rcv[1];
        float i1 = P ? rcv[2] : own[2], f1 = P ? rcv[3] : own[3];
        float g1 = P ? own[2] : rcv[2], o1 = P ? own[3] : rcv[3];
        c[nt][0] = f0 * c[nt][0] + i0 * g0;
        h[nt][0] = o0 * ftanh(c[nt][0]);
        c[nt][1] = f1 * c[nt][1] + i1 * g1;
        h[nt][1] = o1 * ftanh(c[nt][1]);
    }
}

extern __shared__ float smem_f[];

__global__ __launch_bounds__(NT, 1) void lstm2_mma_kernel(
    const float* __restrict__ x,
    const float* __restrict__ w_ih0, const float* __restrict__ w_hh0,
    const float* __restrict__ b_ih0, const float* __restrict__ b_hh0,
    const float* __restrict__ w_ih1, const float* __restrict__ w_hh1,
    const float* __restrict__ b_ih1, const float* __restrict__ b_hh1,
    const float* __restrict__ fc_w,  const float* __restrict__ fc_b,
    float* __restrict__ out)
{
    char* sb = (char*)smem_f;
    const int tid   = threadIdx.x;
    const int w     = tid >> 5;
    const int lane  = tid & 31;
    const int g     = lane >> 2;
    const int tq    = lane & 3;
    const int P     = tq & 1;
    const int uu    = tq >> 1;
    const int bbase = blockIdx.x * BT;

    for (int i = tid; i < SMEM_BYTES / 4; i += NT) ((u32*)sb)[i] = 0u;
    __syncthreads();

    // W1[n=4j+ty][k]: k<50 w_hh0, 50 w_ih0, 51 bias0
    for (int idx = tid; idx < 200 * 52; idx += NT) {
        int n = idx / 52, k = idx - n * 52;
        int row = (n & 3) * 50 + (n >> 2);
        float v = (k < 50) ? w_hh0[row * 50 + k]
                : (k == 50) ? w_ih0[row] : (b_ih0[row] + b_hh0[row]);
        sthalf2(sb + W1H_O, sb + W1L_O, W1RS, n, k, v);
    }
    // W2: k<50 w_ih1, 56..105 w_hh1, 106 bias1
    for (int idx = tid; idx < 200 * 101; idx += NT) {
        int n = idx / 101, kk = idx - n * 101;
        int row = (n & 3) * 50 + (n >> 2);
        int k; float v;
        if (kk < 50)       { k = kk;     v = w_ih1[row * 50 + kk]; }
        else if (kk < 100) { k = kk + 6; v = w_hh1[row * 50 + (kk - 50)]; }
        else               { k = 106;    v = b_ih1[row] + b_hh1[row]; }
        sthalf2(sb + W2H_O, sb + W2L_O, W2RS, n, k, v);
    }
    if (tid < BT) {
        for (int buf = 0; buf < 2; ++buf) {
            *(__half*)(sb + A1T(buf, 0) + tid * A1RS + 51 * 2)  = __float2half_rn(1.0f);
            *(__half*)(sb + A2T(buf, 0) + tid * A2RS + 106 * 2) = __float2half_rn(1.0f);
        }
        sthalf2(sb + A1T(0, 0), sb + A1T(0, 1), A1RS, tid, 50, x[(bbase + tid) * TLEN]);
    }
    for (int k = tid; k < 50; k += NT) ((float*)(sb + FCW_O))[k] = fc_w[k];
    __syncthreads();

    // activation consts: P=0 regs all sigmoid; P=1 regs 0,2 = tanh
    const float sg = P ? 2.0f : 1.0f;
    const float mg = P ? 2.0f : 1.0f;
    const float bg = P ? 1.0f : 0.0f;

    const int n0A = 8 * w, n0B = 8 * (w + 13);
    const int jA = 2 * w + uu, jB = 2 * (w + 13) + uu;
    const int bb0 = P * 16 + g, bb1 = bb0 + 8;

    float c1[2][2] = {{0.f, 0.f}, {0.f, 0.f}};
    float c2[2][2] = {{0.f, 0.f}, {0.f, 0.f}};
    float h1[2][2], h2[2][2];
    float dm[2][2][4], dc[2][2][4];

    for (int t = 0; t < TLEN; ++t) {
        float xn = 0.0f;
        if (tid < BT && t + 1 < TLEN) xn = x[(bbase + tid) * TLEN + t + 1];
        const int cb = t & 1, nb = cb ^ 1;

        // ===== layer 1 =====
#pragma unroll
        for (int a = 0; a < 2; ++a)
#pragma unroll
            for (int b = 0; b < 2; ++b)
#pragma unroll
                for (int r = 0; r < 4; ++r) { dm[a][b][r] = 0.f; dc[a][b][r] = 0.f; }
        gemm_mma<4, A1RS, W1RS>(sb + A1T(cb, 0), sb + A1T(cb, 1),
                                sb + W1H_O, sb + W1L_O, n0A, n0B, g, tq, dm, dc);
        epi_act(dm, dc, P, sg, mg, bg, c1, h1);
        if (jA < 50) {
            sthalf2(sb + A1T(nb, 0), sb + A1T(nb, 1), A1RS, bb0, jA, h1[0][0]);
            sthalf2(sb + A1T(nb, 0), sb + A1T(nb, 1), A1RS, bb1, jA, h1[0][1]);
            sthalf2(sb + A2T(nb, 0), sb + A2T(nb, 1), A2RS, bb0, jA, h1[0][0]);
            sthalf2(sb + A2T(nb, 0), sb + A2T(nb, 1), A2RS, bb1, jA, h1[0][1]);
        }
        if (jB < 50) {
            sthalf2(sb + A1T(nb, 0), sb + A1T(nb, 1), A1RS, bb0, jB, h1[1][0]);
            sthalf2(sb + A1T(nb, 0), sb + A1T(nb, 1), A1RS, bb1, jB, h1[1][1]);
            sthalf2(sb + A2T(nb, 0), sb + A2T(nb, 1), A2RS, bb0, jB, h1[1][0]);
            sthalf2(sb + A2T(nb, 0), sb + A2T(nb, 1), A2RS, bb1, jB, h1[1][1]);
        }
        if (tid < BT && t + 1 < TLEN)
            sthalf2(sb + A1T(nb, 0), sb + A1T(nb, 1), A1RS, tid, 50, xn);
        __syncthreads();

        // ===== layer 2 =====
#pragma unroll
        for (int a = 0; a < 2; ++a)
#pragma unroll
            for (int b = 0; b < 2; ++b)
#pragma unroll
                for (int r = 0; r < 4; ++r) { dm[a][b][r] = 0.f; dc[a][b][r] = 0.f; }
        gemm_mma<7, A2RS, W2RS>(sb + A2T(nb, 0), sb + A2T(nb, 1),
                                sb + W2H_O, sb + W2L_O, n0A, n0B, g, tq, dm, dc);
        epi_act(dm, dc, P, sg, mg, bg, c2, h2);
        // h2 -> A2[cb] cols 56+j (read at step t+1, which reads A2[cb])
        if (jA < 50) {
            sthalf2(sb + A2T(cb, 0), sb + A2T(cb, 1), A2RS, bb0, 56 + jA, h2[0][0]);
            sthalf2(sb + A2T(cb, 0), sb + A2T(cb, 1), A2RS, bb1, 56 + jA, h2[0][1]);
        }
        if (jB < 50) {
            sthalf2(sb + A2T(cb, 0), sb + A2T(cb, 1), A2RS, bb0, 56 + jB, h2[1][0]);
            sthalf2(sb + A2T(cb, 0), sb + A2T(cb, 1), A2RS, bb1, 56 + jB, h2[1][1]);
        }
        __syncthreads();
    }

    // ---- final FC: h2(t=511) was written to A2[cb=1] cols 56..105 ----
    if (tid < BT) {
        const char* hh = sb + A2T(1, 0);
        const char* hl = sb + A2T(1, 1);
        const float* fcs = (const float*)(sb + FCW_O);
        float s = fc_b[0];
        const float inv = 1.0f / 1024.0f;
#pragma unroll 10
        for (int k = 0; k < 50; ++k) {
            float hi = __half2float(*(const __half*)(hh + tid * A2RS + (56 + k) * 2));
            float lo = __half2float(*(const __half*)(hl + tid * A2RS + (56 + k) * 2));
            s += (hi + lo * inv) * fcs[k];
        }
        out[bbase + tid] = s;
    }
}

extern "C" void kernel_launch(void* const* d_in, const int* in_sizes, int n_in,
                              void* d_out, int out_size) {
    const float* x     = (const float*)d_in[0];
    const float* w_ih0 = (const float*)d_in[1];
    const float* w_hh0 = (const float*)d_in[2];
    const float* b_ih0 = (const float*)d_in[3];
    const float* b_hh0 = (const float*)d_in[4];
    const float* w_ih1 = (const float*)d_in[5];
    const float* w_hh1 = (const float*)d_in[6];
    const float* b_ih1 = (const float*)d_in[7];
    const float* b_hh1 = (const float*)d_in[8];
    const float* fc_w  = (const float*)d_in[9];
    const float* fc_b  = (const float*)d_in[10];
    float* out = (float*)d_out;

    cudaFuncSetAttribute(lstm2_mma_kernel,
                         cudaFuncAttributeMaxDynamicSharedMemorySize,
                         SMEM_BYTES);

    lstm2_mma_kernel<<<4096 / BT, NT, SMEM_BYTES>>>(
        x, w_ih0, w_hh0, b_ih0, b_hh0,
        w_ih1, w_hh1, b_ih1, b_hh1, fc_w, fc_b, out);
}

// round 14
// speedup vs baseline: 1.9076x; 1.5461x over previous
#include <cuda_runtime.h>
#include <cuda_fp16.h>
#include <cstdint>

// R14: R13 mma.sync fp16 3-pass + two phase-shifted 16-batch teams
// (13 warps each, named barriers). Per warp: 1 m-tile x 2 n-tiles.

typedef uint32_t u32;

#define NT    832
#define TLEN  512

#define W1H_O 0
#define W1L_O 29952
#define W2H_O 59904
#define W2L_O 109824
#define A1_O  159744
#define A2_O  178176
#define FCW_O 208896
#define SMEM_BYTES 209408

#define A1RS 144
#define A2RS 240
#define W1RS 144
#define W2RS 240
#define A1T(tm, buf, part) (A1_O + ((((tm) * 2 + (buf)) * 2) + (part)) * 2304)
#define A2T(tm, buf, part) (A2_O + ((((tm) * 2 + (buf)) * 2) + (part)) * 3840)

__device__ __forceinline__ float fsig(float v) {
    return __fdividef(1.0f, 1.0f + __expf(-v));
}
__device__ __forceinline__ float ftanh(float v) {
    return __fdividef(2.0f, 1.0f + __expf(-2.0f * v)) - 1.0f;
}

__device__ __forceinline__ void mma16816(float d[4], const u32 a[4], u32 b0, u32 b1) {
    asm("mma.sync.aligned.m16n8k16.row.col.f32.f16.f16.f32 "
        "{%0,%1,%2,%3},{%4,%5,%6,%7},{%8,%9},{%0,%1,%2,%3};"
        : "+f"(d[0]), "+f"(d[1]), "+f"(d[2]), "+f"(d[3])
        : "r"(a[0]), "r"(a[1]), "r"(a[2]), "r"(a[3]), "r"(b0), "r"(b1));
}

__device__ __forceinline__ void sthalf2(char* bh, char* bl, int rs, int row, int col, float v) {
    __half hi = __float2half_rn(v);
    __half lo = __float2half_rn((v - __half2float(hi)) * 1024.0f);
    *(__half*)(bh + row * rs + col * 2) = hi;
    *(__half*)(bl + row * rs + col * 2) = lo;
}

template <int KS, int ARS, int WRS>
__device__ __forceinline__ void gemm_mma(
    const char* ah_b, const char* al_b, const char* wh_b, const char* wl_b,
    int n0A, int n0B, int g, int tq, float dm[2][4], float dc[2][4])
{
#pragma unroll
    for (int ks = 0; ks < KS; ++ks) {
        const int kb = ks * 32 + tq * 4;
        u32 ah[4], al[4];
        const char* p = ah_b + g * ARS + kb;
        ah[0] = *(const u32*)(p);
        ah[1] = *(const u32*)(p + 8 * ARS);
        ah[2] = *(const u32*)(p + 16);
        ah[3] = *(const u32*)(p + 8 * ARS + 16);
        const char* q = al_b + g * ARS + kb;
        al[0] = *(const u32*)(q);
        al[1] = *(const u32*)(q + 8 * ARS);
        al[2] = *(const u32*)(q + 16);
        al[3] = *(const u32*)(q + 8 * ARS + 16);
#pragma unroll
        for (int nn = 0; nn < 2; ++nn) {
            const int n0 = nn ? n0B : n0A;
            const char* pw = wh_b + (n0 + g) * WRS + kb;
            u32 bh0 = *(const u32*)pw, bh1 = *(const u32*)(pw + 16);
            const char* ql = wl_b + (n0 + g) * WRS + kb;
            u32 bl0 = *(const u32*)ql, bl1 = *(const u32*)(ql + 16);
            mma16816(dm[nn], ah, bh0, bh1);
            mma16816(dc[nn], al, bh0, bh1);
            mma16816(dc[nn], ah, bl0, bl1);
        }
    }
}

// P=0 owns batch-row g, P=1 owns g+8; shfl.xor(1) completes (i,f,g,o).
__device__ __forceinline__ void epi_act(
    float dm[2][4], float dc[2][4], int P, float sg, float mg, float bg,
    float c[2], float h[2])
{
    const float inv = 1.0f / 1024.0f;
#pragma unroll
    for (int nt = 0; nt < 2; ++nt) {
        float v0 = mg * fsig(sg * (dm[nt][0] + dc[nt][0] * inv)) - bg;
        float v1 = fsig(dm[nt][1] + dc[nt][1] * inv);
        float v2 = mg * fsig(sg * (dm[nt][2] + dc[nt][2] * inv)) - bg;
        float v3 = fsig(dm[nt][3] + dc[nt][3] * inv);
        float s0 = P ? v0 : v2, s1 = P ? v1 : v3;
        float r0 = __shfl_xor_sync(0xffffffffu, s0, 1);
        float r1 = __shfl_xor_sync(0xffffffffu, s1, 1);
        float iv = P ? r0 : v0, fv = P ? r1 : v1;
        float gv = P ? v2 : r0, ov = P ? v3 : r1;
        c[nt] = fv * c[nt] + iv * gv;
        h[nt] = ov * ftanh(c[nt]);
    }
}

extern __shared__ float smem_f[];

__global__ __launch_bounds__(NT, 1) void lstm2_mma_kernel(
    const float* __restrict__ x,
    const float* __restrict__ w_ih0, const float* __restrict__ w_hh0,
    const float* __restrict__ b_ih0, const float* __restrict__ b_hh0,
    const float* __restrict__ w_ih1, const float* __restrict__ w_hh1,
    const float* __restrict__ b_ih1, const float* __restrict__ b_hh1,
    const float* __restrict__ fc_w,  const float* __restrict__ fc_b,
    float* __restrict__ out)
{
    char* sb = (char*)smem_f;
    const int tid   = threadIdx.x;
    const int w     = tid >> 5;
    const int lane  = tid & 31;
    const int g     = lane >> 2;
    const int tq    = lane & 3;
    const int P     = tq & 1;
    const int uu    = tq >> 1;
    const int team  = (w >= 13);
    const int tw    = w - team * 13;
    const int ttid  = tid - team * 416;
    const int bbase = blockIdx.x * 32;

    for (int i = tid; i < SMEM_BYTES / 4; i += NT) ((u32*)sb)[i] = 0u;
    __syncthreads();

    // W1[n=4j+ty][k]: k<50 w_hh0, 50 w_ih0, 51 bias0
    for (int idx = tid; idx < 200 * 52; idx += NT) {
        int n = idx / 52, k = idx - n * 52;
        int row = (n & 3) * 50 + (n >> 2);
        float v = (k < 50) ? w_hh0[row * 50 + k]
                : (k == 50) ? w_ih0[row] : (b_ih0[row] + b_hh0[row]);
        sthalf2(sb + W1H_O, sb + W1L_O, W1RS, n, k, v);
    }
    // W2: k<50 w_ih1, 56..105 w_hh1, 106 bias1
    for (int idx = tid; idx < 200 * 101; idx += NT) {
        int n = idx / 101, kk = idx - n * 101;
        int row = (n & 3) * 50 + (n >> 2);
        int k; float v;
        if (kk < 50)       { k = kk;     v = w_ih1[row * 50 + kk]; }
        else if (kk < 100) { k = kk + 6; v = w_hh1[row * 50 + (kk - 50)]; }
        else               { k = 106;    v = b_ih1[row] + b_hh1[row]; }
        sthalf2(sb + W2H_O, sb + W2L_O, W2RS, n, k, v);
    }
    if (tid < 64) {  // bias-one cols, all teams/bufs, rows 0..15
        int tm = tid >> 5, buf = (tid >> 4) & 1, row = tid & 15;
        *(__half*)(sb + A1T(tm, buf, 0) + row * A1RS + 51 * 2)  = __float2half_rn(1.0f);
        *(__half*)(sb + A2T(tm, buf, 0) + row * A2RS + 106 * 2) = __float2half_rn(1.0f);
    }
    if (tid < 32) {  // x_0
        int tm = tid >> 4, row = tid & 15;
        sthalf2(sb + A1T(tm, 0, 0), sb + A1T(tm, 0, 1), A1RS, row, 50,
                x[(bbase + tid) * TLEN]);
    }
    for (int k = tid; k < 50; k += NT) ((float*)(sb + FCW_O))[k] = fc_w[k];
    __syncthreads();

    const float sg = P ? 2.0f : 1.0f;
    const float mg = P ? 2.0f : 1.0f;
    const float bg = P ? 1.0f : 0.0f;

    const int n0A = 8 * tw, n0B = 8 * (tw + 13);
    const int jA = 2 * tw + uu, jB = 2 * (tw + 13) + uu;
    const int brow = P ? g + 8 : g;

    float c1[2] = {0.f, 0.f}, c2[2] = {0.f, 0.f};
    float h1[2], h2[2];
    float dm[2][4], dc[2][4];

    for (int t = 0; t < TLEN; ++t) {
        float xn = 0.0f;
        if (ttid < 16 && t + 1 < TLEN)
            xn = x[(bbase + team * 16 + ttid) * TLEN + t + 1];
        const int cb = t & 1, nb = cb ^ 1;

        // ===== layer 1 =====
#pragma unroll
        for (int a = 0; a < 2; ++a)
#pragma unroll
            for (int r = 0; r < 4; ++r) { dm[a][r] = 0.f; dc[a][r] = 0.f; }
        gemm_mma<4, A1RS, W1RS>(sb + A1T(team, cb, 0), sb + A1T(team, cb, 1),
                                sb + W1H_O, sb + W1L_O, n0A, n0B, g, tq, dm, dc);
        epi_act(dm, dc, P, sg, mg, bg, c1, h1);
        if (jA < 50) {
            sthalf2(sb + A1T(team, nb, 0), sb + A1T(team, nb, 1), A1RS, brow, jA, h1[0]);
            sthalf2(sb + A2T(team, nb, 0), sb + A2T(team, nb, 1), A2RS, brow, jA, h1[0]);
        }
        if (jB < 50) {
            sthalf2(sb + A1T(team, nb, 0), sb + A1T(team, nb, 1), A1RS, brow, jB, h1[1]);
            sthalf2(sb + A2T(team, nb, 0), sb + A2T(team, nb, 1), A2RS, brow, jB, h1[1]);
        }
        if (ttid < 16 && t + 1 < TLEN)
            sthalf2(sb + A1T(team, nb, 0), sb + A1T(team, nb, 1), A1RS, ttid, 50, xn);
        asm volatile("bar.sync %0, 416;" :: "r"(1 + team) : "memory");

        // ===== layer 2 =====
#pragma unroll
        for (int a = 0; a < 2; ++a)
#pragma unroll
            for (int r = 0; r < 4; ++r) { dm[a][r] = 0.f; dc[a][r] = 0.f; }
        gemm_mma<7, A2RS, W2RS>(sb + A2T(team, nb, 0), sb + A2T(team, nb, 1),
                                sb + W2H_O, sb + W2L_O, n0A, n0B, g, tq, dm, dc);
        epi_act(dm, dc, P, sg, mg, bg, c2, h2);
        if (jA < 50) {
            sthalf2(sb + A2T(team, cb, 0), sb + A2T(team, cb, 1), A2RS, brow, 56 + jA, h2[0]);
        }
        if (jB < 50) {
            sthalf2(sb + A2T(team, cb, 0), sb + A2T(team, cb, 1), A2RS, brow, 56 + jB, h2[1]);
        }
        asm volatile("bar.sync %0, 416;" :: "r"(1 + team) : "memory");
    }

    // ---- final FC: h2(511) in A2T(team, 1, .) cols 56..105 ----
    __syncthreads();
    if (tid < 32) {
        int tm = tid >> 4, row = tid & 15;
        const char* hh = sb + A2T(tm, 1, 0);
        const char* hl = sb + A2T(tm, 1, 1);
        const float* fcs = (const float*)(sb + FCW_O);
        float s = fc_b[0];
        const float inv = 1.0f / 1024.0f;
#pragma unroll 10
        for (int k = 0; k < 50; ++k) {
            float hi = __half2float(*(const __half*)(hh + row * A2RS + (56 + k) * 2));
            float lo = __half2float(*(const __half*)(hl + row * A2RS + (56 + k) * 2));
            s += (hi + lo * inv) * fcs[k];
        }
        out[bbase + tid] = s;
    }
}

extern "C" void kernel_launch(void* const* d_in, const int* in_sizes, int n_in,
                              void* d_out, int out_size) {
    const float* x     = (const float*)d_in[0];
    const float* w_ih0 = (const float*)d_in[1];
    const float* w_hh0 = (const float*)d_in[2];
    const float* b_ih0 = (const float*)d_in[3];
    const float* b_hh0 = (const float*)d_in[4];
    const float* w_ih1 = (const float*)d_in[5];
    const float* w_hh1 = (const float*)d_in[6];
    const float* b_ih1 = (const float*)d_in[7];
    const float* b_hh1 = (const float*)d_in[8];
    const float* fc_w  = (const float*)d_in[9];
    const float* fc_b  = (const float*)d_in[10];
    float* out = (float*)d_out;

    cudaFuncSetAttribute(lstm2_mma_kernel,
                         cudaFuncAttributeMaxDynamicSharedMemorySize,
                         SMEM_BYTES);

    lstm2_mma_kernel<<<128, NT, SMEM_BYTES>>>(
        x, w_ih0, w_hh0, b_ih0, b_hh0,
        w_ih1, w_hh1, b_ih1, b_hh1, fc_w, fc_b, out);
}